// round 1
// baseline (speedup 1.0000x reference)
#include <cuda_runtime.h>

// ColorRestoration: per-row 14-tap windowed correlation + shifted-z copy.
//   y[c,h,w]   = sum_{u=w-13..w, u>=0} x[h,u+rc]*z[h,u]  /  sum z[h,u]
//   rgb[c,h,w] = z[h, w-rc]   (0 if w<rc),  rc in {3,7,10}
// Output layout: y (3,H,W) then rgb_filter (3,H,W), float32, concatenated.

#define IMG_W 3072
#define IMG_H 2048
#define SEG   1024
#define HALO  16
#define SMEMN (SEG + 2 * HALO)   // 1056 floats per array

__global__ __launch_bounds__(256, 4)
void color_restore_kernel(const float* __restrict__ x,
                          const float* __restrict__ z,
                          float* __restrict__ out)
{
    __shared__ float sx[SMEMN];
    __shared__ float sz[SMEMN];

    const int h   = blockIdx.y;
    const int gw0 = blockIdx.x * SEG;          // segment start (multiple of 1024)
    const int t   = threadIdx.x;

    const float* __restrict__ xrow = x + (size_t)h * IMG_W;
    const float* __restrict__ zrow = z + (size_t)h * IMG_W;

    // ---- cooperative staged load (float4, zero-filled halo) ----
    // shared index s corresponds to global w = gw0 - HALO + s
    for (int v = t; v < SMEMN / 4; v += 256) {
        const int g = gw0 - HALO + 4 * v;      // float4-aligned (gw0 mult of 1024)
        float4 xv, zv;
        if (g >= 0 && g + 3 < IMG_W) {
            xv = *reinterpret_cast<const float4*>(xrow + g);
            zv = *reinterpret_cast<const float4*>(zrow + g);
        } else {
            float tx[4], tz[4];
            #pragma unroll
            for (int j = 0; j < 4; ++j) {
                const int gg = g + j;
                const bool ok = (gg >= 0) && (gg < IMG_W);
                tx[j] = ok ? xrow[gg] : 0.0f;
                tz[j] = ok ? zrow[gg] : 0.0f;
            }
            xv = make_float4(tx[0], tx[1], tx[2], tx[3]);
            zv = make_float4(tz[0], tz[1], tz[2], tz[3]);
        }
        *reinterpret_cast<float4*>(sx + 4 * v) = xv;
        *reinterpret_cast<float4*>(sz + 4 * v) = zv;
    }
    __syncthreads();

    // ---- per-thread: 4 consecutive outputs at w0 = gw0 + 4t ----
    const int sI = HALO + 4 * t;               // shared idx of w0 (mult of 4)

    // z window: zr[j] = z[w0 - 16 + j], j = 0..19   (5 aligned LDS.128)
    float zr[20];
    #pragma unroll
    for (int q = 0; q < 5; ++q) {
        const float4 v = *reinterpret_cast<const float4*>(sz + (sI - 16) + 4 * q);
        zr[4 * q + 0] = v.x; zr[4 * q + 1] = v.y;
        zr[4 * q + 2] = v.z; zr[4 * q + 3] = v.w;
    }
    // x window: xr[j] = x[w0 - 12 + j], j = 0..27   (7 aligned LDS.128)
    float xr[28];
    #pragma unroll
    for (int q = 0; q < 7; ++q) {
        const float4 v = *reinterpret_cast<const float4*>(sx + (sI - 12) + 4 * q);
        xr[4 * q + 0] = v.x; xr[4 * q + 1] = v.y;
        xr[4 * q + 2] = v.z; xr[4 * q + 3] = v.w;
    }

    // init window sum ending at w0: u = w0-13+k, k=0..13
    //   z[u]      -> zr[3+k]
    //   x[u+3]    -> xr[k+2],  x[u+7] -> xr[k+6],  x[u+10] -> xr[k+9]
    float den = 0.0f, n3 = 0.0f, n7 = 0.0f, n10 = 0.0f;
    #pragma unroll
    for (int k = 0; k < 14; ++k) {
        const float zu = zr[3 + k];
        den += zu;
        n3  = fmaf(xr[k + 2], zu, n3);
        n7  = fmaf(xr[k + 6], zu, n7);
        n10 = fmaf(xr[k + 9], zu, n10);
    }

    float y3a[4], y7a[4], y10a[4], f3a[4], f7a[4], f10a[4];
    {
        const float r = 1.0f / den;
        y3a[0] = n3 * r;  y7a[0] = n7 * r;  y10a[0] = n10 * r;
        f3a[0] = zr[13];  f7a[0] = zr[9];   f10a[0] = zr[6];
    }
    // slide: add u_new = w0+i (z=zr[16+i]), drop u_old = w0+i-14 (z=zr[2+i])
    #pragma unroll
    for (int i = 1; i < 4; ++i) {
        const float zn = zr[16 + i];
        const float zo = zr[2 + i];
        den += zn - zo;
        n3  = fmaf(xr[15 + i], zn, fmaf(-xr[1 + i], zo, n3));
        n7  = fmaf(xr[19 + i], zn, fmaf(-xr[5 + i], zo, n7));
        n10 = fmaf(xr[22 + i], zn, fmaf(-xr[8 + i], zo, n10));
        const float r = 1.0f / den;
        y3a[i] = n3 * r;   y7a[i] = n7 * r;   y10a[i] = n10 * r;
        f3a[i] = zr[13 + i]; f7a[i] = zr[9 + i]; f10a[i] = zr[6 + i];
    }

    // ---- coalesced float4 stores ----
    const size_t HW   = (size_t)IMG_H * IMG_W;
    const size_t base = (size_t)h * IMG_W + gw0 + 4 * t;
    *reinterpret_cast<float4*>(out + 0 * HW + base) = *reinterpret_cast<float4*>(y3a);
    *reinterpret_cast<float4*>(out + 1 * HW + base) = *reinterpret_cast<float4*>(y7a);
    *reinterpret_cast<float4*>(out + 2 * HW + base) = *reinterpret_cast<float4*>(y10a);
    *reinterpret_cast<float4*>(out + 3 * HW + base) = *reinterpret_cast<float4*>(f3a);
    *reinterpret_cast<float4*>(out + 4 * HW + base) = *reinterpret_cast<float4*>(f7a);
    *reinterpret_cast<float4*>(out + 5 * HW + base) = *reinterpret_cast<float4*>(f10a);
}

extern "C" void kernel_launch(void* const* d_in, const int* in_sizes, int n_in,
                              void* d_out, int out_size)
{
    (void)in_sizes; (void)n_in; (void)out_size;
    const float* x = (const float*)d_in[0];
    const float* z = (const float*)d_in[1];
    float* out = (float*)d_out;

    dim3 grid(IMG_W / SEG, IMG_H);   // (3, 2048)
    color_restore_kernel<<<grid, 256>>>(x, z, out);
}